// round 6
// baseline (speedup 1.0000x reference)
#include <cuda_runtime.h>
#include <cstdint>

// ---------------------------------------------------------------------------
// DistancePredictor: out[b,i,j,n] = relu(xi[b,i,:]*xj[b,j,:]) @ Wo[:,n] + bo[n]
//   xi = x@Wi + bi, xj = x@Wj + bj
// B=2, L=384, D=1280, H=256, NB=10
// ---------------------------------------------------------------------------

#define B_   2
#define L_   384
#define D_   1280
#define H_   256
#define NB_  10
#define ROWS_ (B_ * L_)        // 768
#define SPLITK_ 8
#define KCH_ (D_ / SPLITK_)    // 160

__device__ __align__(16) float g_xi[ROWS_ * H_];
__device__ __align__(16) float g_xj[ROWS_ * H_];
__device__ __align__(16) float g_part[2 * SPLITK_ * ROWS_ * H_];   // 12.6 MB

// ---- packed f32x2 helpers -------------------------------------------------
typedef unsigned long long u64;

__device__ __forceinline__ u64 pk2(float a, float b) {
    u64 r;
    asm("mov.b64 %0, {%1, %2};"
        : "=l"(r) : "r"(__float_as_uint(a)), "r"(__float_as_uint(b)));
    return r;
}
__device__ __forceinline__ void fma2(u64& d, u64 a, u64 b) {
    asm("fma.rn.f32x2 %0, %1, %2, %0;" : "+l"(d) : "l"(a), "l"(b));
}
__device__ __forceinline__ u64 add2(u64 a, u64 b) {
    u64 d;
    asm("add.rn.f32x2 %0, %1, %2;" : "=l"(d) : "l"(a), "l"(b));
    return d;
}

// ---------------------------------------------------------------------------
// Stage 1: partial GEMM, 128x128 tile, 256 threads, 8x8/thread, BK=16.
// grid (2, 6, 16): x = n-tile, y = m-tile, z = split(0..7) | proj(<<3).
// ---------------------------------------------------------------------------
__global__ __launch_bounds__(256) void proj_kernel(
    const float* __restrict__ X,
    const float* __restrict__ Wi, const float* __restrict__ Wj)
{
    const int split = blockIdx.z & 7;
    const int pj    = blockIdx.z >> 3;
    const float* W  = pj ? Wj : Wi;
    float* P = g_part + (size_t)(pj * SPLITK_ + split) * ROWS_ * H_;

    __shared__ __align__(16) float As[16][132];   // [k][m]  (132*4B = 16B-mult)
    __shared__ __align__(16) float Bs[16][132];   // [k][n]

    const int tid = threadIdx.x;
    const int tx  = tid & 15;        // n group
    const int ty  = tid >> 4;        // m group
    const int m0  = blockIdx.y * 128;
    const int n0  = blockIdx.x * 128;
    const int kb  = split * KCH_;

    u64 acc[8][4];
    #pragma unroll
    for (int r = 0; r < 8; r++)
        #pragma unroll
        for (int c = 0; c < 4; c++) acc[r][c] = 0ull;

    // A loader: k uniform per warp (conflict-free STS), m = lane-contiguous
    const int a_row = tid & 63;            // m (two passes +64)
    const int a_k4  = (tid >> 6) << 2;     // 0,4,8,12
    // B loader: k uniform per warp, n lane-contiguous (STS.128 conflict-free)
    const int b_k   = tid >> 5;            // 0..7 (+8)
    const int b_n4  = (tid & 31) << 2;     // 0..124

    for (int k0 = 0; k0 < KCH_; k0 += 16) {
        float4 av[2], bv[2];
        #pragma unroll
        for (int p = 0; p < 2; p++)
            av[p] = *(const float4*)&X[(m0 + a_row + p * 64) * D_ + kb + k0 + a_k4];
        #pragma unroll
        for (int p = 0; p < 2; p++)
            bv[p] = *(const float4*)&W[(kb + k0 + b_k + p * 8) * H_ + n0 + b_n4];

        __syncthreads();
        #pragma unroll
        for (int p = 0; p < 2; p++) {
            int m = a_row + p * 64;
            As[a_k4 + 0][m] = av[p].x;
            As[a_k4 + 1][m] = av[p].y;
            As[a_k4 + 2][m] = av[p].z;
            As[a_k4 + 3][m] = av[p].w;
            *(float4*)&Bs[b_k + p * 8][b_n4] = bv[p];
        }
        __syncthreads();

        #pragma unroll
        for (int kk = 0; kk < 16; kk++) {
            // two 4-wide fragments spaced 64 apart (conflict-free LDS.128)
            float4 a0 = *(const float4*)&As[kk][ty << 2];
            float4 a1 = *(const float4*)&As[kk][(ty << 2) + 64];
            float4 b0 = *(const float4*)&Bs[kk][tx << 2];
            float4 b1 = *(const float4*)&Bs[kk][(tx << 2) + 64];
            u64 b2[4] = { pk2(b0.x, b0.y), pk2(b0.z, b0.w),
                          pk2(b1.x, b1.y), pk2(b1.z, b1.w) };
            float aval[8] = { a0.x, a0.y, a0.z, a0.w, a1.x, a1.y, a1.z, a1.w };
            #pragma unroll
            for (int r = 0; r < 8; r++) {
                u64 ad = pk2(aval[r], aval[r]);
                #pragma unroll
                for (int c = 0; c < 4; c++) fma2(acc[r][c], ad, b2[c]);
            }
        }
    }

    // epilogue: rows ty*4 + {0..3} and +64; cols tx*4 + {0..3} and +64
    #pragma unroll
    for (int r = 0; r < 8; r++) {
        int m = m0 + ((r < 4) ? (ty << 2) + r : (ty << 2) + 64 + (r - 4));
        float* dst = &P[(size_t)m * H_ + n0 + (tx << 2)];
        *(u64*)&dst[0]      = acc[r][0];
        *(u64*)&dst[2]      = acc[r][1];
        *(u64*)&dst[64]     = acc[r][2];
        *(u64*)&dst[66]     = acc[r][3];
    }
}

// ---------------------------------------------------------------------------
// Stage 1b: reduce 8 split-K partials + bias -> g_xi / g_xj
// ---------------------------------------------------------------------------
__global__ __launch_bounds__(256) void reduce_kernel(
    const float* __restrict__ bi, const float* __restrict__ bj)
{
    const int pj   = blockIdx.y;
    const int q    = blockIdx.x * 256 + threadIdx.x;
    const int flat = q << 2;

    const float* base = g_part + (size_t)pj * SPLITK_ * ROWS_ * H_;
    float4 s = *(const float4*)&base[flat];
    #pragma unroll
    for (int sp = 1; sp < SPLITK_; sp++) {
        float4 v = *(const float4*)&base[(size_t)sp * ROWS_ * H_ + flat];
        s.x += v.x; s.y += v.y; s.z += v.z; s.w += v.w;
    }
    const float* bias = pj ? bj : bi;
    float4 bv = *(const float4*)&bias[flat & (H_ - 1)];
    s.x += bv.x; s.y += bv.y; s.z += bv.z; s.w += bv.w;

    float* dst = pj ? g_xj : g_xi;
    *(float4*)&dst[flat] = s;
}

// ---------------------------------------------------------------------------
// Stage 2: out[b,i,j,:] = relu(xi_i ∘ xj_j) @ Wo + bo
// Block: 16 i x 128 j, 256 thr (warp w -> i pair {2w,2w+1}, lane -> 4 j).
// ALL of Xj (256h x 128j), Xi, Wo staged in 160 KB dynamic smem; ONE barrier.
// Grid (3, 24, 2) = 144 blocks = one wave.
// ---------------------------------------------------------------------------
#define XJ_STRIDE 132              // pad: conflict-free loads AND stores
#define XI_STRIDE 18

__global__ __launch_bounds__(256) void pair_kernel(
    const float* __restrict__ Wo, const float* __restrict__ bo,
    float* __restrict__ out)
{
    extern __shared__ __align__(16) float sm[];
    float* XjT  = sm;                                  // [256][132]
    float* XiT  = sm + 256 * XJ_STRIDE;                // [256][18]
    float* Wo_s = XiT + 256 * XI_STRIDE;               // [2560]

    const int tid  = threadIdx.x;
    const int w    = tid >> 5;
    const int lane = tid & 31;
    const int b    = blockIdx.z;
    const int i0   = blockIdx.y * 16;
    const int j0   = blockIdx.x * 128;

    // ---- stage XjT: thread -> j = tid>>1, h-offset = (tid&1)*4, step 8 ----
    {
        const int jl  = tid >> 1;
        const int hof = (tid & 1) << 2;        // 0 or 4
        const float* src = &g_xj[(size_t)(b * L_ + j0 + jl) * H_];
        #pragma unroll
        for (int q = 0; q < 32; q++) {
            int h = hof + q * 8;
            float4 v = *(const float4*)&src[h];
            XjT[(h + 0) * XJ_STRIDE + jl] = v.x;
            XjT[(h + 1) * XJ_STRIDE + jl] = v.y;
            XjT[(h + 2) * XJ_STRIDE + jl] = v.z;
            XjT[(h + 3) * XJ_STRIDE + jl] = v.w;
        }
    }
    // ---- stage XiT (transposed, i-pairs adjacent) ----
    {
        const int il = tid >> 4;               // 0..15
        const int hb = (tid & 15) << 2;
        const float* src = &g_xi[(size_t)(b * L_ + i0 + il) * H_];
        #pragma unroll
        for (int p = 0; p < 4; p++) {
            int h = hb + p * 64;
            float4 v = *(const float4*)&src[h];
            XiT[(h + 0) * XI_STRIDE + il] = v.x;
            XiT[(h + 1) * XI_STRIDE + il] = v.y;
            XiT[(h + 2) * XI_STRIDE + il] = v.z;
            XiT[(h + 3) * XI_STRIDE + il] = v.w;
        }
    }
    for (int q = tid; q < H_ * NB_; q += 256) Wo_s[q] = Wo[q];

    u64 bo2[5];
    #pragma unroll
    for (int c = 0; c < 5; c++) bo2[c] = pk2(bo[2 * c], bo[2 * c + 1]);

    u64 acc[2][4][5];
    #pragma unroll
    for (int ii = 0; ii < 2; ii++)
        #pragma unroll
        for (int jj = 0; jj < 4; jj++)
            #pragma unroll
            for (int c = 0; c < 5; c++) acc[ii][jj][c] = 0ull;

    __syncthreads();    // the ONLY barrier

    #pragma unroll 4
    for (int hg = 0; hg < H_; hg++) {
        float2 xi = *(const float2*)&XiT[hg * XI_STRIDE + (w << 1)];
        float4 xj = *(const float4*)&XjT[hg * XJ_STRIDE + (lane << 2)];

        float pa0 = fmaxf(xi.x * xj.x, 0.0f);
        float pa1 = fmaxf(xi.x * xj.y, 0.0f);
        float pa2 = fmaxf(xi.x * xj.z, 0.0f);
        float pa3 = fmaxf(xi.x * xj.w, 0.0f);
        float pb0 = fmaxf(xi.y * xj.x, 0.0f);
        float pb1 = fmaxf(xi.y * xj.y, 0.0f);
        float pb2 = fmaxf(xi.y * xj.z, 0.0f);
        float pb3 = fmaxf(xi.y * xj.w, 0.0f);
        u64 pa[4] = { pk2(pa0, pa0), pk2(pa1, pa1), pk2(pa2, pa2), pk2(pa3, pa3) };
        u64 pb[4] = { pk2(pb0, pb0), pk2(pb1, pb1), pk2(pb2, pb2), pk2(pb3, pb3) };

        const float* wr = &Wo_s[hg * NB_];
        #pragma unroll
        for (int c = 0; c < 5; c++) {
            u64 wo2 = *(const u64*)&wr[2 * c];
            fma2(acc[0][0][c], pa[0], wo2);
            fma2(acc[0][1][c], pa[1], wo2);
            fma2(acc[0][2][c], pa[2], wo2);
            fma2(acc[0][3][c], pa[3], wo2);
            fma2(acc[1][0][c], pb[0], wo2);
            fma2(acc[1][1][c], pb[1], wo2);
            fma2(acc[1][2][c], pb[2], wo2);
            fma2(acc[1][3][c], pb[3], wo2);
        }
    }

    // Epilogue
    #pragma unroll
    for (int ii = 0; ii < 2; ii++) {
        const int i = i0 + (w << 1) + ii;
        size_t base = ((size_t)(b * L_ + i) * L_ + j0 + (lane << 2)) * NB_;
        #pragma unroll
        for (int jj = 0; jj < 4; jj++) {
            #pragma unroll
            for (int c = 0; c < 5; c++) {
                u64 v = add2(acc[ii][jj][c], bo2[c]);
                *(u64*)&out[base + jj * NB_ + 2 * c] = v;
            }
        }
    }
}

// ---------------------------------------------------------------------------
extern "C" void kernel_launch(void* const* d_in, const int* in_sizes, int n_in,
                              void* d_out, int out_size)
{
    const float* x  = (const float*)d_in[0];
    const float* Wi = (const float*)d_in[1];
    const float* bi = (const float*)d_in[2];
    const float* Wj = (const float*)d_in[3];
    const float* bj = (const float*)d_in[4];
    const float* Wo = (const float*)d_in[5];
    const float* bo = (const float*)d_in[6];
    float* out = (float*)d_out;

    const int pair_smem = (256 * XJ_STRIDE + 256 * XI_STRIDE + H_ * NB_) * 4;
    cudaFuncSetAttribute(pair_kernel,
                         cudaFuncAttributeMaxDynamicSharedMemorySize, pair_smem);

    proj_kernel<<<dim3(2, 6, 2 * SPLITK_), 256>>>(x, Wi, Wj);
    reduce_kernel<<<dim3(192, 2), 256>>>(bi, bj);
    pair_kernel<<<dim3(L_ / 128, L_ / 16, B_), 256, pair_smem>>>(Wo, bo, out);
}